// round 4
// baseline (speedup 1.0000x reference)
#include <cuda_runtime.h>

// Problem constants (input is (8,3,512,512) fp32)
constexpr int HH = 512;
constexpr int WW = 512;
constexpr int NB = 9;       // orientation bins
constexpr int OH = 32;      // HOG grid (stride 16, 33-tap window over reflect-padded)
constexpr int OW = 32;
constexpr int BMAX = 8;

#define PIF 3.14159265358979323846f   // rounds to fp32 pi (0x40490FDB)

// ---------------- scratch (static device globals; no allocation) ----------------
__device__ float g_gray[BMAX * HH * WW];     // 8.4 MB
__device__ float g_int [BMAX * HH * WW];     // gradient magnitude
__device__ float g_ori [BMAX * HH * WW];     // orientation in degrees [0,180)
__device__ float g_hog [BMAX * NB * OH * OW];
__device__ float g_maxn[BMAX];
__device__ float g_q   [BMAX * 2 * OH * OW]; // quantized dominant-direction planes
__device__ float g_tmp [BMAX * 2 * OH * WW]; // horizontal-resize intermediate
__device__ float g_wt  [WW * 6];             // lanczos3 weights per output coord
__device__ int   g_ws  [WW];                 // first tap index per output coord

// ---------------- stage 1a: grayscale ----------------
__global__ void gray_kernel(const float* __restrict__ x, int B) {
    int i = blockIdx.x * blockDim.x + threadIdx.x;
    int n = B * HH * WW;
    if (i >= n) return;
    int b = i / (HH * WW);
    int p = i - b * (HH * WW);
    const float* xb = x + (size_t)b * 3 * HH * WW;
    float g = 0.299f * xb[p] + 0.587f * xb[p + HH * WW] + 0.114f * xb[p + 2 * HH * WW];
    g_gray[i] = g;
}

// ---------------- stage 1b: gradients -> intensity, orientation ----------------
__global__ void grad_kernel(int B) {
    int i = blockIdx.x * blockDim.x + threadIdx.x;
    int n = B * HH * WW;
    if (i >= n) return;
    int p = i % (HH * WW);
    int y = p / WW;
    int xx = p - y * WW;
    const float* gb = g_gray + (i - p);  // batch base
    float gl = (xx > 0)      ? gb[p - 1]  : 0.0f;
    float gr = (xx < WW - 1) ? gb[p + 1]  : 0.0f;
    float gu = (y > 0)       ? gb[p - WW] : 0.0f;
    float gd = (y < HH - 1)  ? gb[p + WW] : 0.0f;
    float gx = gr - gl;
    float gy = gd - gu;
    float inten = sqrtf(gx * gx + gy * gy);
    // orientation = mod(atan2(gy,gx)+pi, pi) / pi * 180   (all fp32, like reference)
    float a = atan2f(gy, gx) + PIF;          // >= 0
    float r = fmodf(a, PIF);                 // jnp.mod for positive args == fmod
    float o = r / PIF * 180.0f;
    g_int[i] = inten;
    g_ori[i] = o;
}

// reflect index (numpy 'reflect', no edge repeat) into [0, HH-1]
__device__ __forceinline__ int refl(int m) {
    m = (m < 0) ? -m : m;
    m = (m > HH - 1) ? (2 * (HH - 1) - m) : m;
    return m;
}

// ---------------- stage 2: HOG aggregation (33x33 tent, stride 16, reflect pad) ----------------
__global__ void hog_kernel() {
    int b = blockIdx.y;
    int cell = blockIdx.x;          // 0..1023
    int oy = cell >> 5;
    int ox = cell & 31;
    const float* Ip = g_int + b * HH * WW;
    const float* Op = g_ori + b * HH * WW;
    int y0 = oy * 16 - 16;
    int x0 = ox * 16 - 16;

    float acc[NB];
#pragma unroll
    for (int k = 0; k < NB; k++) acc[k] = 0.0f;

    for (int t = threadIdx.x; t < 33 * 33; t += blockDim.x) {
        int dy = t / 33;
        int dx = t - dy * 33;
        int py = refl(y0 + dy);
        int px = refl(x0 + dx);
        int gi = py * WW + px;
        float I = Ip[gi];
        float o = Op[gi];
        float fy = (float)(dy - 16), fx = (float)(dx - 16);
        // numpy fp32: 1 - sqrt(d2) / (16*sqrt(2))
        float filt = 1.0f - sqrtf(fy * fy + fx * fx) / 22.62741699796952f;
        // tent bins: weight_k = clip(1 - |o - (10+20k)|*9/180, 0, 1); <=2 bins nonzero
        int k0 = (int)floorf((o - 10.0f) * 0.05f);     // candidate bins k0, k0+1
        float c0 = 10.0f + 20.0f * (float)k0;
        float wa = fminf(fmaxf(1.0f - (fabsf(o - c0) * 9.0f) / 180.0f, 0.0f), 1.0f);
        float wb = fminf(fmaxf(1.0f - (fabsf(o - (c0 + 20.0f)) * 9.0f) / 180.0f, 0.0f), 1.0f);
        float ca = (k0 >= 0)      ? filt * (wa * I) : 0.0f;
        float cb = (k0 + 1 <= 8)  ? filt * (wb * I) : 0.0f;
        int k1 = k0 + 1;
#pragma unroll
        for (int k = 0; k < NB; k++) {
            float add = (k == k0) ? ca : ((k == k1) ? cb : 0.0f);
            acc[k] += add;
        }
    }

    // block reduce (8 warps of 32)
#pragma unroll
    for (int k = 0; k < NB; k++) {
#pragma unroll
        for (int off = 16; off > 0; off >>= 1)
            acc[k] += __shfl_down_sync(0xffffffffu, acc[k], off);
    }
    __shared__ float sm[NB][8];
    int lane = threadIdx.x & 31, warp = threadIdx.x >> 5;
    if (lane == 0) {
#pragma unroll
        for (int k = 0; k < NB; k++) sm[k][warp] = acc[k];
    }
    __syncthreads();
    if (threadIdx.x < NB) {
        float s = 0.0f;
#pragma unroll
        for (int w = 0; w < 8; w++) s += sm[threadIdx.x][w];
        g_hog[(b * NB + threadIdx.x) * (OH * OW) + oy * OW + ox] = s;
    }
}

// ---------------- stage 3a: per-batch max pixel L2-norm over bins ----------------
__global__ void maxn_kernel() {
    int b = blockIdx.x;
    int p = threadIdx.x;  // 1024 threads = all pixels
    float s = 0.0f;
#pragma unroll
    for (int k = 0; k < NB; k++) {
        float v = g_hog[(b * NB + k) * (OH * OW) + p];
        s += v * v;
    }
    float val = sqrtf(s);
    __shared__ float sm[32];
    int lane = threadIdx.x & 31, warp = threadIdx.x >> 5;
#pragma unroll
    for (int off = 16; off > 0; off >>= 1)
        val = fmaxf(val, __shfl_down_sync(0xffffffffu, val, off));
    if (lane == 0) sm[warp] = val;
    __syncthreads();
    if (warp == 0) {
        val = sm[lane];
#pragma unroll
        for (int off = 16; off > 0; off >>= 1)
            val = fmaxf(val, __shfl_down_sync(0xffffffffu, val, off));
        if (lane == 0) g_maxn[b] = val;
    }
}

// ---------------- stage 3b: dominant direction + quantize ----------------
__global__ void dom_kernel(int B) {
    int i = blockIdx.x * blockDim.x + threadIdx.x;
    if (i >= B * OH * OW) return;
    int b = i / (OH * OW);
    int p = i - b * (OH * OW);
    float maxn = g_maxn[b];
    float A = 0.0f, Cc = 0.0f, Bs = 0.0f;
#pragma unroll
    for (int k = 0; k < NB; k++) {
        float ck = 10.0f + 20.0f * (float)k;
        float th = (ck / 180.0f) * PIF;
        float s = sinf(th), c = cosf(th);
        float hn = g_hog[(b * NB + k) * (OH * OW) + p] / maxn;
        float h2 = hn * hn;
        A  += (s * s) * h2;
        Cc += (c * c) * h2;
        Bs += (s * c) * h2;
    }
    float Bb = -Bs;
    float half = (A - Cc) * 0.5f;
    float lam = (A + Cc) * 0.5f + sqrtf(half * half + Bb * Bb);
    float la = lam - A, lc = lam - Cc;
    float n1 = Bb * Bb + la * la;
    float n2 = lc * lc + Bb * Bb;
    bool use1 = (n1 >= n2);
    float vx = use1 ? Bb : lc;
    float vy = use1 ? la : Bb;
    float nrm = sqrtf(vx * vx + vy * vy) + 1e-9f;
    float dx = vx / nrm, dy = vy / nrm;
    g_q[(b * 2 + 0) * (OH * OW) + p] = floorf((dx + 1.0f) / 2.0f * 255.0f);
    g_q[(b * 2 + 1) * (OH * OW) + p] = floorf((dy + 1.0f) / 2.0f * 255.0f);
}

// ---------------- stage 4a: lanczos3 weights (replicates jax compute_weight_mat, fp32) ----------------
__global__ void wt_kernel() {
    int o = threadIdx.x;
    if (o >= WW) return;
    float sf = (o + 0.5f) * 0.0625f - 0.5f;   // exact in fp32
    int i0 = (int)floorf(sf) - 2;             // 6 taps, |sf - i| < 3 strictly
    float w[6];
    float tot = 0.0f;
#pragma unroll
    for (int j = 0; j < 6; j++) {
        int i = i0 + j;
        float val = 0.0f;
        if (i >= 0 && i < OW) {
            float x = fabsf(sf - (float)i);
            float px1 = PIF * x;
            float s1 = (x == 0.0f) ? 1.0f : (sinf(px1) / px1);
            float x3 = x / 3.0f;
            float px3 = PIF * x3;
            float s3 = (x3 == 0.0f) ? 1.0f : (sinf(px3) / px3);
            val = 3.0f * s1 * s3;
        }
        w[j] = val;
        tot += val;   // jax normalizes by plain sum over valid rows
    }
#pragma unroll
    for (int j = 0; j < 6; j++) g_wt[o * 6 + j] = w[j] / tot;
    g_ws[o] = i0;
}

// ---------------- stage 4b: horizontal resize pass (32x32 -> 32x512) ----------------
__global__ void hpass_kernel(int B) {
    int i = blockIdx.x * blockDim.x + threadIdx.x;
    int n = B * 2 * OH * WW;
    if (i >= n) return;
    int xo = i % WW;
    int rest = i / WW;
    int row = rest % OH;
    int bc = rest / OH;     // b*2 + c
    int st = g_ws[xo];
    const float* qrow = g_q + bc * (OH * OW) + row * OW;
    float s = 0.0f;
#pragma unroll
    for (int j = 0; j < 6; j++) {
        int idx = min(max(st + j, 0), OW - 1);  // weight is 0 for invalid taps
        s += g_wt[xo * 6 + j] * qrow[idx];
    }
    g_tmp[i] = s;
}

// ---------------- stage 4c: vertical pass + round/clip + channel-normalize ----------------
__global__ void vpass_kernel(float* __restrict__ out, int B) {
    int i = blockIdx.x * blockDim.x + threadIdx.x;
    int n = B * HH * WW;
    if (i >= n) return;
    int x = i % WW;
    int y = (i / WW) % HH;
    int b = i / (HH * WW);
    int st = g_ws[y];
    const float* t0 = g_tmp + (b * 2 + 0) * (OH * WW);
    const float* t1 = g_tmp + (b * 2 + 1) * (OH * WW);
    float r0 = 0.0f, r1 = 0.0f;
#pragma unroll
    for (int j = 0; j < 6; j++) {
        int idx = min(max(st + j, 0), OH - 1);
        float wj = g_wt[y * 6 + j];
        r0 += wj * t0[idx * WW + x];
        r1 += wj * t1[idx * WW + x];
    }
    r0 = fminf(fmaxf(rintf(r0), 0.0f), 255.0f);   // jnp.round = half-even = rintf
    r1 = fminf(fmaxf(rintf(r1), 0.0f), 255.0f);
    float o0 = (r0 / 255.0f - 0.5f) * 2.0f;
    float o1 = (r1 / 255.0f - 0.5f) * 2.0f;
    float nn = sqrtf(o0 * o0 + o1 * o1);
    out[((size_t)(b * 2 + 0) * HH + y) * WW + x] = o0 / nn;
    out[((size_t)(b * 2 + 1) * HH + y) * WW + x] = o1 / nn;
}

// ---------------- launch ----------------
extern "C" void kernel_launch(void* const* d_in, const int* in_sizes, int n_in,
                              void* d_out, int out_size) {
    const float* x = (const float*)d_in[0];
    int B = in_sizes[0] / (3 * HH * WW);
    if (B > BMAX) B = BMAX;
    int npix = B * HH * WW;

    gray_kernel<<<(npix + 255) / 256, 256>>>(x, B);
    grad_kernel<<<(npix + 255) / 256, 256>>>(B);
    wt_kernel<<<1, 512>>>();
    hog_kernel<<<dim3(OH * OW, B), 256>>>();
    maxn_kernel<<<B, 1024>>>();
    dom_kernel<<<(B * OH * OW + 255) / 256, 256>>>(B);
    hpass_kernel<<<(B * 2 * OH * WW + 255) / 256, 256>>>(B);
    vpass_kernel<<<(npix + 255) / 256, 256>>>((float*)d_out, B);
}

// round 5
// speedup vs baseline: 1.1267x; 1.1267x over previous
#include <cuda_runtime.h>

constexpr int HH = 512;
constexpr int WW = 512;
constexpr int NB = 9;
constexpr int OH = 32;
constexpr int OW = 32;
constexpr int BMAX = 8;

#define PIF 3.14159265358979323846f

// ---------------- scratch ----------------
__device__ float2 g_vab[BMAX * HH * WW];           // (wa*I, wb*I) per pixel
__device__ unsigned char g_k0[BMAX * HH * WW];     // base bin in [0,7]
__device__ float g_filt[33 * 33];                  // radial tent LUT
__device__ float g_hog [BMAX * NB * OH * OW];
__device__ float g_maxn[BMAX];
__device__ float g_q   [BMAX * 2 * OH * OW];
__device__ float g_tmp [BMAX * 2 * OH * WW];
__device__ float g_wt  [WW * 6];
__device__ int   g_ws  [WW];

// ---------------- init: tent filter LUT ----------------
__global__ void init_kernel() {
    int t = blockIdx.x * blockDim.x + threadIdx.x;
    if (t < 33 * 33) {
        int dy = t / 33, dx = t - (t / 33) * 33;
        float fy = (float)(dy - 16), fx = (float)(dx - 16);
        g_filt[t] = 1.0f - sqrtf(fy * fy + fx * fx) / 22.627417f;
    }
}

// ---------------- fused grayscale + gradient + bin decomposition ----------------
__global__ void grad_kernel(const float* __restrict__ x) {
    __shared__ float sg[10][34];
    int b = blockIdx.z;
    int x0 = blockIdx.x * 32, y0 = blockIdx.y * 8;
    const float* xb = x + (size_t)b * 3 * HH * WW;
    int tid = threadIdx.y * 32 + threadIdx.x;

    // load gray tile with halo; zero outside (matches zero-padded gradients)
    for (int i = tid; i < 10 * 34; i += 256) {
        int ly = i / 34, lx = i - ly * 34;
        int gy = y0 + ly - 1, gx = x0 + lx - 1;
        float v = 0.0f;
        if (gy >= 0 && gy < HH && gx >= 0 && gx < WW) {
            int p = gy * WW + gx;
            v = 0.299f * xb[p] + 0.587f * xb[p + HH * WW] + 0.114f * xb[p + 2 * HH * WW];
        }
        sg[ly][lx] = v;
    }
    __syncthreads();

    int lx = threadIdx.x, ly = threadIdx.y;
    float gx = sg[ly + 1][lx + 2] - sg[ly + 1][lx];
    float gy = sg[ly + 2][lx + 1] - sg[ly][lx + 1];
    float inten = sqrtf(gx * gx + gy * gy);
    float a = atan2f(gy, gx) + PIF;      // >= 0
    float r = fmodf(a, PIF);             // jnp.mod (positive arg) == fmod
    float o = r / PIF * 180.0f;          // [0,180)

    int k0 = (int)floorf((o - 10.0f) * 0.05f);   // [-1,8]
    float c0 = 10.0f + 20.0f * (float)k0;
    float wa = fminf(fmaxf(1.0f - (fabsf(o - c0) * 9.0f) / 180.0f, 0.0f), 1.0f);
    float wb = fminf(fmaxf(1.0f - (fabsf(o - (c0 + 20.0f)) * 9.0f) / 180.0f, 0.0f), 1.0f);
    float va = wa * inten, vb = wb * inten;
    // remap so both scatter targets k0, k0+1 are valid bins in [0,8]
    if (k0 < 0)      { k0 = 0; va = vb; vb = 0.0f; }  // only bin 0 active (weight wb)
    else if (k0 > 7) { k0 = 7; vb = va; va = 0.0f; }  // only bin 8 active (weight wa)

    int p = b * HH * WW + (y0 + ly) * WW + (x0 + lx);
    g_vab[p] = make_float2(va, vb);
    g_k0[p] = (unsigned char)k0;
}

__device__ __forceinline__ int refl(int m) {
    m = (m < 0) ? -m : m;
    m = (m > HH - 1) ? (2 * (HH - 1) - m) : m;
    return m;
}

// ---------------- HOG aggregation: gather + shared scatter ----------------
__global__ void hog_kernel() {
    __shared__ float sacc[256 * NB];   // per-thread bin partials
    __shared__ int srow[33], scol[33];
    int b = blockIdx.y;
    int cell = blockIdx.x;
    int oy = cell >> 5, ox = cell & 31;
    int tid = threadIdx.x;

    if (tid < 33) {
        srow[tid] = refl(oy * 16 - 16 + tid) * WW;
        scol[tid] = refl(ox * 16 - 16 + tid);
    }
#pragma unroll
    for (int k = 0; k < NB; k++) sacc[tid * NB + k] = 0.0f;
    __syncthreads();

    const float2* __restrict__ V = g_vab + b * HH * WW;
    const unsigned char* __restrict__ K = g_k0 + b * HH * WW;
    float* my = sacc + tid * NB;

    // 1089 taps: 4 guaranteed per thread (tid + j*256 < 1024) + tail of 65
    float2 v[4]; float f[4]; int kk[4];
#pragma unroll
    for (int j = 0; j < 4; j++) {
        int t = tid + j * 256;
        int dy = t / 33;
        int dx = t - dy * 33;
        int gi = srow[dy] + scol[dx];
        v[j] = __ldg(&V[gi]);
        kk[j] = (int)K[gi];
        f[j] = __ldg(&g_filt[t]);
    }
#pragma unroll
    for (int j = 0; j < 4; j++) {
        my[kk[j]]     += f[j] * v[j].x;
        my[kk[j] + 1] += f[j] * v[j].y;
    }
    if (tid < 65) {
        int t = 1024 + tid;
        int dy = t / 33;
        int dx = t - dy * 33;
        int gi = srow[dy] + scol[dx];
        float2 vt = __ldg(&V[gi]);
        int kt = (int)K[gi];
        float ft = __ldg(&g_filt[t]);
        my[kt]     += ft * vt.x;
        my[kt + 1] += ft * vt.y;
    }
    __syncthreads();

    // tree reduce 256 partial rows -> row 0
    for (int s = 128; s >= 1; s >>= 1) {
        if (tid < s) {
#pragma unroll
            for (int k = 0; k < NB; k++)
                sacc[tid * NB + k] += sacc[(tid + s) * NB + k];
        }
        __syncthreads();
    }
    if (tid < NB)
        g_hog[(b * NB + tid) * (OH * OW) + cell] = sacc[tid];
}

// ---------------- per-batch max pixel L2-norm over bins ----------------
__global__ void maxn_kernel() {
    int b = blockIdx.x;
    int p = threadIdx.x;
    float s = 0.0f;
#pragma unroll
    for (int k = 0; k < NB; k++) {
        float v = g_hog[(b * NB + k) * (OH * OW) + p];
        s += v * v;
    }
    float val = sqrtf(s);
    __shared__ float sm[32];
    int lane = threadIdx.x & 31, warp = threadIdx.x >> 5;
#pragma unroll
    for (int off = 16; off > 0; off >>= 1)
        val = fmaxf(val, __shfl_down_sync(0xffffffffu, val, off));
    if (lane == 0) sm[warp] = val;
    __syncthreads();
    if (warp == 0) {
        val = sm[lane];
#pragma unroll
        for (int off = 16; off > 0; off >>= 1)
            val = fmaxf(val, __shfl_down_sync(0xffffffffu, val, off));
        if (lane == 0) g_maxn[b] = val;
    }
}

// ---------------- dominant direction + quantize ----------------
__global__ void dom_kernel(int B) {
    int i = blockIdx.x * blockDim.x + threadIdx.x;
    if (i >= B * OH * OW) return;
    int b = i / (OH * OW);
    int p = i - b * (OH * OW);
    float maxn = g_maxn[b];
    float A = 0.0f, Cc = 0.0f, Bs = 0.0f;
#pragma unroll
    for (int k = 0; k < NB; k++) {
        float ck = 10.0f + 20.0f * (float)k;
        float th = (ck / 180.0f) * PIF;
        float s = sinf(th), c = cosf(th);
        float hn = g_hog[(b * NB + k) * (OH * OW) + p] / maxn;
        float h2 = hn * hn;
        A  += (s * s) * h2;
        Cc += (c * c) * h2;
        Bs += (s * c) * h2;
    }
    float Bb = -Bs;
    float half = (A - Cc) * 0.5f;
    float lam = (A + Cc) * 0.5f + sqrtf(half * half + Bb * Bb);
    float la = lam - A, lc = lam - Cc;
    float n1 = Bb * Bb + la * la;
    float n2 = lc * lc + Bb * Bb;
    bool use1 = (n1 >= n2);
    float vx = use1 ? Bb : lc;
    float vy = use1 ? la : Bb;
    float nrm = sqrtf(vx * vx + vy * vy) + 1e-9f;
    float dx = vx / nrm, dy = vy / nrm;
    g_q[(b * 2 + 0) * (OH * OW) + p] = floorf((dx + 1.0f) / 2.0f * 255.0f);
    g_q[(b * 2 + 1) * (OH * OW) + p] = floorf((dy + 1.0f) / 2.0f * 255.0f);
}

// ---------------- lanczos3 weights (fp32, matches jax compute_weight_mat) ----------------
__global__ void wt_kernel() {
    int o = threadIdx.x;
    if (o >= WW) return;
    float sf = (o + 0.5f) * 0.0625f - 0.5f;
    int i0 = (int)floorf(sf) - 2;
    float w[6];
    float tot = 0.0f;
#pragma unroll
    for (int j = 0; j < 6; j++) {
        int i = i0 + j;
        float val = 0.0f;
        if (i >= 0 && i < OW) {
            float xx = fabsf(sf - (float)i);
            float px1 = PIF * xx;
            float s1 = (xx == 0.0f) ? 1.0f : (sinf(px1) / px1);
            float x3 = xx / 3.0f;
            float px3 = PIF * x3;
            float s3 = (x3 == 0.0f) ? 1.0f : (sinf(px3) / px3);
            val = 3.0f * s1 * s3;
        }
        w[j] = val;
        tot += val;
    }
#pragma unroll
    for (int j = 0; j < 6; j++) g_wt[o * 6 + j] = w[j] / tot;
    g_ws[o] = i0;
}

// ---------------- horizontal resize pass ----------------
__global__ void hpass_kernel(int B) {
    int i = blockIdx.x * blockDim.x + threadIdx.x;
    int n = B * 2 * OH * WW;
    if (i >= n) return;
    int xo = i % WW;
    int rest = i / WW;
    int row = rest % OH;
    int bc = rest / OH;
    int st = g_ws[xo];
    const float* qrow = g_q + bc * (OH * OW) + row * OW;
    float s = 0.0f;
#pragma unroll
    for (int j = 0; j < 6; j++) {
        int idx = min(max(st + j, 0), OW - 1);
        s += g_wt[xo * 6 + j] * qrow[idx];
    }
    g_tmp[i] = s;
}

// ---------------- vertical pass + round/clip + normalize ----------------
__global__ void vpass_kernel(float* __restrict__ out, int B) {
    int i = blockIdx.x * blockDim.x + threadIdx.x;
    int n = B * HH * WW;
    if (i >= n) return;
    int x = i % WW;
    int y = (i / WW) % HH;
    int b = i / (HH * WW);
    int st = g_ws[y];
    const float* t0 = g_tmp + (b * 2 + 0) * (OH * WW);
    const float* t1 = g_tmp + (b * 2 + 1) * (OH * WW);
    float r0 = 0.0f, r1 = 0.0f;
#pragma unroll
    for (int j = 0; j < 6; j++) {
        int idx = min(max(st + j, 0), OH - 1);
        float wj = g_wt[y * 6 + j];
        r0 += wj * t0[idx * WW + x];
        r1 += wj * t1[idx * WW + x];
    }
    r0 = fminf(fmaxf(rintf(r0), 0.0f), 255.0f);
    r1 = fminf(fmaxf(rintf(r1), 0.0f), 255.0f);
    float o0 = (r0 / 255.0f - 0.5f) * 2.0f;
    float o1 = (r1 / 255.0f - 0.5f) * 2.0f;
    float nn = sqrtf(o0 * o0 + o1 * o1);
    out[((size_t)(b * 2 + 0) * HH + y) * WW + x] = o0 / nn;
    out[((size_t)(b * 2 + 1) * HH + y) * WW + x] = o1 / nn;
}

// ---------------- launch ----------------
extern "C" void kernel_launch(void* const* d_in, const int* in_sizes, int n_in,
                              void* d_out, int out_size) {
    const float* x = (const float*)d_in[0];
    int B = in_sizes[0] / (3 * HH * WW);
    if (B > BMAX) B = BMAX;
    int npix = B * HH * WW;

    init_kernel<<<5, 256>>>();
    wt_kernel<<<1, 512>>>();
    grad_kernel<<<dim3(WW / 32, HH / 8, B), dim3(32, 8)>>>(x);
    hog_kernel<<<dim3(OH * OW, B), 256>>>();
    maxn_kernel<<<B, 1024>>>();
    dom_kernel<<<(B * OH * OW + 255) / 256, 256>>>(B);
    hpass_kernel<<<(B * 2 * OH * WW + 255) / 256, 256>>>(B);
    vpass_kernel<<<(npix + 255) / 256, 256>>>((float*)d_out, B);
}

// round 6
// speedup vs baseline: 1.3440x; 1.1928x over previous
#include <cuda_runtime.h>

constexpr int HH = 512;
constexpr int WW = 512;
constexpr int NB = 9;
constexpr int OH = 32;
constexpr int OW = 32;
constexpr int BMAX = 8;

#define PIF 3.14159265358979323846f

// ---------------- scratch ----------------
__device__ float2 g_vab[BMAX * HH * WW];           // (wa*I, wb*I) per pixel
__device__ unsigned char g_k0[BMAX * HH * WW];     // base bin in [0,7]
__device__ float g_hog [BMAX * NB * OH * OW];
__device__ float g_q   [BMAX * 2 * OH * OW];
__device__ float g_tmp [BMAX * 2 * OH * WW];
__device__ float g_wt  [WW * 6];
__device__ int   g_ws  [WW];

// ---------------- fused grayscale + gradient + bin decomposition ----------------
__global__ void grad_kernel(const float* __restrict__ x) {
    __shared__ float sg[10][34];
    int b = blockIdx.z;
    int x0 = blockIdx.x * 32, y0 = blockIdx.y * 8;
    const float* xb = x + (size_t)b * 3 * HH * WW;
    int tid = threadIdx.y * 32 + threadIdx.x;

    for (int i = tid; i < 10 * 34; i += 256) {
        int ly = i / 34, lx = i - ly * 34;
        int gy = y0 + ly - 1, gx = x0 + lx - 1;
        float v = 0.0f;
        if (gy >= 0 && gy < HH && gx >= 0 && gx < WW) {
            int p = gy * WW + gx;
            v = 0.299f * xb[p] + 0.587f * xb[p + HH * WW] + 0.114f * xb[p + 2 * HH * WW];
        }
        sg[ly][lx] = v;
    }
    __syncthreads();

    int lx = threadIdx.x, ly = threadIdx.y;
    float gx = sg[ly + 1][lx + 2] - sg[ly + 1][lx];
    float gy = sg[ly + 2][lx + 1] - sg[ly][lx + 1];
    float inten = sqrtf(gx * gx + gy * gy);
    float a = atan2f(gy, gx) + PIF;      // >= 0
    float r = fmodf(a, PIF);             // jnp.mod (positive arg) == fmod
    float o = r / PIF * 180.0f;          // [0,180)

    int k0 = (int)floorf((o - 10.0f) * 0.05f);   // [-1,8]
    float c0 = 10.0f + 20.0f * (float)k0;
    float wa = fminf(fmaxf(1.0f - (fabsf(o - c0) * 9.0f) / 180.0f, 0.0f), 1.0f);
    float wb = fminf(fmaxf(1.0f - (fabsf(o - (c0 + 20.0f)) * 9.0f) / 180.0f, 0.0f), 1.0f);
    float va = wa * inten, vb = wb * inten;
    if (k0 < 0)      { k0 = 0; va = vb; vb = 0.0f; }
    else if (k0 > 7) { k0 = 7; vb = va; va = 0.0f; }

    int p = b * HH * WW + (y0 + ly) * WW + (x0 + lx);
    g_vab[p] = make_float2(va, vb);
    g_k0[p] = (unsigned char)k0;
}

__device__ __forceinline__ int refl(int m) {
    m = (m < 0) ? -m : m;
    m = (m > HH - 1) ? (2 * (HH - 1) - m) : m;
    return m;
}

// ---------------- HOG aggregation: gather + conflict-free shared scatter ----------------
__global__ void hog_kernel() {
    __shared__ float sacc[NB][256];     // bank(tid) independent of bin -> conflict-free
    __shared__ int srow[33], scol[33];
    int b = blockIdx.y;
    int cell = blockIdx.x;
    int oy = cell >> 5, ox = cell & 31;
    int tid = threadIdx.x;

    if (tid < 33) {
        srow[tid] = refl(oy * 16 - 16 + tid) * WW;
        scol[tid] = refl(ox * 16 - 16 + tid);
    }
#pragma unroll
    for (int k = 0; k < NB; k++) sacc[k][tid] = 0.0f;
    __syncthreads();

    const float2* __restrict__ V = g_vab + b * HH * WW;
    const unsigned char* __restrict__ K = g_k0 + b * HH * WW;

    // 1089 taps: 4 per thread + tail of 65
    float2 v[4]; float f[4]; int kk[4];
#pragma unroll
    for (int j = 0; j < 4; j++) {
        int t = tid + j * 256;
        int dy = t / 33;
        int dx = t - dy * 33;
        int gi = srow[dy] + scol[dx];
        v[j] = __ldg(&V[gi]);
        kk[j] = (int)K[gi];
        float fy = (float)(dy - 16), fx = (float)(dx - 16);
        f[j] = 1.0f - sqrtf(fy * fy + fx * fx) / 22.627417f;
    }
#pragma unroll
    for (int j = 0; j < 4; j++) {
        sacc[kk[j]][tid]     += f[j] * v[j].x;
        sacc[kk[j] + 1][tid] += f[j] * v[j].y;
    }
    if (tid < 65) {
        int t = 1024 + tid;
        int dy = t / 33;
        int dx = t - dy * 33;
        int gi = srow[dy] + scol[dx];
        float2 vt = __ldg(&V[gi]);
        int kt = (int)K[gi];
        float fy = (float)(dy - 16), fx = (float)(dx - 16);
        float ft = 1.0f - sqrtf(fy * fy + fx * fx) / 22.627417f;
        sacc[kt][tid]     += ft * vt.x;
        sacc[kt + 1][tid] += ft * vt.y;
    }
    __syncthreads();

    // warp w reduces bins k = w, w+8 (strided LDS + shuffle tree)
    int w = tid >> 5, l = tid & 31;
    for (int k = w; k < NB; k += 8) {
        float s = 0.0f;
#pragma unroll
        for (int i = 0; i < 8; i++) s += sacc[k][l + 32 * i];
#pragma unroll
        for (int off = 16; off > 0; off >>= 1)
            s += __shfl_down_sync(0xffffffffu, s, off);
        if (l == 0)
            g_hog[(b * NB + k) * (OH * OW) + cell] = s;
    }
}

// ---------------- fused per-batch max-norm + dominant direction + quantize ----------------
__global__ void maxdom_kernel() {
    int b = blockIdx.x;
    int p = threadIdx.x;   // 1024 = all cells of this batch
    __shared__ float sm[32];
    __shared__ float smax;

    float hv[NB];
    float s = 0.0f;
#pragma unroll
    for (int k = 0; k < NB; k++) {
        hv[k] = g_hog[(b * NB + k) * (OH * OW) + p];
        s += hv[k] * hv[k];
    }
    float val = sqrtf(s);
    int lane = p & 31, warp = p >> 5;
#pragma unroll
    for (int off = 16; off > 0; off >>= 1)
        val = fmaxf(val, __shfl_down_sync(0xffffffffu, val, off));
    if (lane == 0) sm[warp] = val;
    __syncthreads();
    if (warp == 0) {
        val = sm[lane];
#pragma unroll
        for (int off = 16; off > 0; off >>= 1)
            val = fmaxf(val, __shfl_down_sync(0xffffffffu, val, off));
        if (lane == 0) smax = val;
    }
    __syncthreads();
    float maxn = smax;

    float A = 0.0f, Cc = 0.0f, Bs = 0.0f;
#pragma unroll
    for (int k = 0; k < NB; k++) {
        float ck = 10.0f + 20.0f * (float)k;
        float th = (ck / 180.0f) * PIF;
        float sn = sinf(th), cs = cosf(th);
        float hn = hv[k] / maxn;
        float h2 = hn * hn;
        A  += (sn * sn) * h2;
        Cc += (cs * cs) * h2;
        Bs += (sn * cs) * h2;
    }
    float Bb = -Bs;
    float half = (A - Cc) * 0.5f;
    float lam = (A + Cc) * 0.5f + sqrtf(half * half + Bb * Bb);
    float la = lam - A, lc = lam - Cc;
    float n1 = Bb * Bb + la * la;
    float n2 = lc * lc + Bb * Bb;
    bool use1 = (n1 >= n2);
    float vx = use1 ? Bb : lc;
    float vy = use1 ? la : Bb;
    float nrm = sqrtf(vx * vx + vy * vy) + 1e-9f;
    float dx = vx / nrm, dy = vy / nrm;
    g_q[(b * 2 + 0) * (OH * OW) + p] = floorf((dx + 1.0f) / 2.0f * 255.0f);
    g_q[(b * 2 + 1) * (OH * OW) + p] = floorf((dy + 1.0f) / 2.0f * 255.0f);
}

// ---------------- lanczos3 weights (fp32, matches jax compute_weight_mat) ----------------
__global__ void wt_kernel() {
    int o = threadIdx.x;
    if (o >= WW) return;
    float sf = (o + 0.5f) * 0.0625f - 0.5f;
    int i0 = (int)floorf(sf) - 2;
    float w[6];
    float tot = 0.0f;
#pragma unroll
    for (int j = 0; j < 6; j++) {
        int i = i0 + j;
        float val = 0.0f;
        if (i >= 0 && i < OW) {
            float xx = fabsf(sf - (float)i);
            float px1 = PIF * xx;
            float s1 = (xx == 0.0f) ? 1.0f : (sinf(px1) / px1);
            float x3 = xx / 3.0f;
            float px3 = PIF * x3;
            float s3 = (x3 == 0.0f) ? 1.0f : (sinf(px3) / px3);
            val = 3.0f * s1 * s3;
        }
        w[j] = val;
        tot += val;
    }
#pragma unroll
    for (int j = 0; j < 6; j++) g_wt[o * 6 + j] = w[j] / tot;
    g_ws[o] = i0;
}

// ---------------- horizontal resize pass ----------------
__global__ void hpass_kernel(int B) {
    int i = blockIdx.x * blockDim.x + threadIdx.x;
    int n = B * 2 * OH * WW;
    if (i >= n) return;
    int xo = i % WW;
    int rest = i / WW;
    int row = rest % OH;
    int bc = rest / OH;
    int st = g_ws[xo];
    const float* qrow = g_q + bc * (OH * OW) + row * OW;
    float s = 0.0f;
#pragma unroll
    for (int j = 0; j < 6; j++) {
        int idx = min(max(st + j, 0), OW - 1);
        s += g_wt[xo * 6 + j] * qrow[idx];
    }
    g_tmp[i] = s;
}

// ---------------- vertical pass + round/clip + normalize ----------------
__global__ void vpass_kernel(float* __restrict__ out, int B) {
    int i = blockIdx.x * blockDim.x + threadIdx.x;
    int n = B * HH * WW;
    if (i >= n) return;
    int x = i % WW;
    int y = (i / WW) % HH;
    int b = i / (HH * WW);
    int st = g_ws[y];
    const float* t0 = g_tmp + (b * 2 + 0) * (OH * WW);
    const float* t1 = g_tmp + (b * 2 + 1) * (OH * WW);
    float r0 = 0.0f, r1 = 0.0f;
#pragma unroll
    for (int j = 0; j < 6; j++) {
        int idx = min(max(st + j, 0), OH - 1);
        float wj = g_wt[y * 6 + j];
        r0 += wj * t0[idx * WW + x];
        r1 += wj * t1[idx * WW + x];
    }
    r0 = fminf(fmaxf(rintf(r0), 0.0f), 255.0f);
    r1 = fminf(fmaxf(rintf(r1), 0.0f), 255.0f);
    float o0 = (r0 / 255.0f - 0.5f) * 2.0f;
    float o1 = (r1 / 255.0f - 0.5f) * 2.0f;
    float nn = sqrtf(o0 * o0 + o1 * o1);
    out[((size_t)(b * 2 + 0) * HH + y) * WW + x] = o0 / nn;
    out[((size_t)(b * 2 + 1) * HH + y) * WW + x] = o1 / nn;
}

// ---------------- launch ----------------
extern "C" void kernel_launch(void* const* d_in, const int* in_sizes, int n_in,
                              void* d_out, int out_size) {
    const float* x = (const float*)d_in[0];
    int B = in_sizes[0] / (3 * HH * WW);
    if (B > BMAX) B = BMAX;
    int npix = B * HH * WW;

    wt_kernel<<<1, 512>>>();
    grad_kernel<<<dim3(WW / 32, HH / 8, B), dim3(32, 8)>>>(x);
    hog_kernel<<<dim3(OH * OW, B), 256>>>();
    maxdom_kernel<<<B, 1024>>>();
    hpass_kernel<<<(B * 2 * OH * WW + 255) / 256, 256>>>(B);
    vpass_kernel<<<(npix + 255) / 256, 256>>>((float*)d_out, B);
}